// round 7
// baseline (speedup 1.0000x reference)
#include <cuda_runtime.h>
#include <cuda_bf16.h>

#define NN 1000000
#define NE 16000000

// -------- scratch (device globals; no allocation allowed) --------
__device__ float2 g_aggc[NN];    // {sum of x[src], count}
__device__ float4 g_h1[NN];
__device__ float4 g_sum2[NN];
__device__ float4 g_h2[NN];
__device__ float2 g_p3[NN];      // h2 @ W3l (projected to dim 2 before scatter)
__device__ float2 g_sum3[NN];    // accumulated projected values
__device__ float  g_inv[NN];     // 1 / max(count, 1)

__device__ __forceinline__ void red_add_v2(float2* addr, float a, float b) {
    asm volatile("red.global.add.v2.f32 [%0], {%1, %2};"
                 :: "l"(addr), "f"(a), "f"(b) : "memory");
}
__device__ __forceinline__ void red_add_v4(float4* addr, float4 v) {
    asm volatile("red.global.add.v4.f32 [%0], {%1, %2, %3, %4};"
                 :: "l"(addr), "f"(v.x), "f"(v.y), "f"(v.z), "f"(v.w) : "memory");
}

// -------- zero accumulators (upfront: also warms L2 for the scatter) --------
__global__ void k_zero() {
    int i = blockIdx.x * blockDim.x + threadIdx.x;
    if (i >= NN / 2) return;
    float4 z = make_float4(0.f, 0.f, 0.f, 0.f);
    ((float4*)g_aggc)[i] = z;
    ((float4*)g_sum2)[2 * i] = z;
    ((float4*)g_sum2)[2 * i + 1] = z;
    ((float4*)g_sum3)[i] = z;
}

// -------- pass 1: scatter {x[src], 1} to aggc[dst], 4 edges/thread --------
__global__ void k_edge1(const int4* __restrict__ src4,
                        const int4* __restrict__ dst4,
                        const float* __restrict__ x) {
    int t = blockIdx.x * blockDim.x + threadIdx.x;
    if (t >= NE / 4) return;
    int4 s = src4[t];
    int4 d = dst4[t];
    float x0 = __ldg(&x[s.x]);
    float x1 = __ldg(&x[s.y]);
    float x2 = __ldg(&x[s.z]);
    float x3 = __ldg(&x[s.w]);
    red_add_v2(&g_aggc[d.x], x0, 1.0f);
    red_add_v2(&g_aggc[d.y], x1, 1.0f);
    red_add_v2(&g_aggc[d.z], x2, 1.0f);
    red_add_v2(&g_aggc[d.w], x3, 1.0f);
}

// -------- node 1: h1 = relu(mean1*W1l + b1 + x*W1r), 4 nodes/thread --------
__global__ void k_node1(const float* __restrict__ x,
                        const float* __restrict__ W1l, const float* __restrict__ b1,
                        const float* __restrict__ W1r) {
    int t = blockIdx.x * blockDim.x + threadIdx.x;
    if (t >= NN / 4) return;
    float4 ac01 = ((const float4*)g_aggc)[2 * t];
    float4 ac23 = ((const float4*)g_aggc)[2 * t + 1];
    float4 xv   = ((const float4*)x)[t];

    float wl0 = __ldg(&W1l[0]), wl1 = __ldg(&W1l[1]), wl2 = __ldg(&W1l[2]), wl3 = __ldg(&W1l[3]);
    float bb0 = __ldg(&b1[0]),  bb1 = __ldg(&b1[1]),  bb2 = __ldg(&b1[2]),  bb3 = __ldg(&b1[3]);
    float wr0 = __ldg(&W1r[0]), wr1 = __ldg(&W1r[1]), wr2 = __ldg(&W1r[2]), wr3 = __ldg(&W1r[3]);

    float sums[4] = {ac01.x, ac01.z, ac23.x, ac23.z};
    float cnts[4] = {ac01.y, ac01.w, ac23.y, ac23.w};
    float xs[4]   = {xv.x, xv.y, xv.z, xv.w};
    float4 invv;
    #pragma unroll
    for (int k = 0; k < 4; k++) {
        float inv = 1.0f / fmaxf(cnts[k], 1.0f);
        ((float*)&invv)[k] = inv;
        float m = sums[k] * inv;
        float xi = xs[k];
        float4 h;
        h.x = fmaxf(m * wl0 + bb0 + xi * wr0, 0.f);
        h.y = fmaxf(m * wl1 + bb1 + xi * wr1, 0.f);
        h.z = fmaxf(m * wl2 + bb2 + xi * wr2, 0.f);
        h.w = fmaxf(m * wl3 + bb3 + xi * wr3, 0.f);
        g_h1[4 * t + k] = h;
    }
    ((float4*)g_inv)[t] = invv;
}

// -------- pass 2: sum2[dst] += h1[src], 4 edges/thread --------
__global__ void k_edge2(const int4* __restrict__ src4,
                        const int4* __restrict__ dst4) {
    int t = blockIdx.x * blockDim.x + threadIdx.x;
    if (t >= NE / 4) return;
    int4 s = src4[t];
    int4 d = dst4[t];
    float4 v0 = g_h1[s.x];
    float4 v1 = g_h1[s.y];
    float4 v2 = g_h1[s.z];
    float4 v3 = g_h1[s.w];
    red_add_v4(&g_sum2[d.x], v0);
    red_add_v4(&g_sum2[d.y], v1);
    red_add_v4(&g_sum2[d.z], v2);
    red_add_v4(&g_sum2[d.w], v3);
}

// -------- node 2: h2 = relu(mean2@W2l + b2 + h1@W2r); p3 = h2@W3l; 4 nodes/thread --------
__global__ void k_node2(const float* __restrict__ W2l, const float* __restrict__ b2,
                        const float* __restrict__ W2r, const float* __restrict__ W3l) {
    int t = blockIdx.x * blockDim.x + threadIdx.x;
    if (t >= NN / 4) return;
    float4 invv = ((const float4*)g_inv)[t];

    float wl[16], wr[16], bb[4], w3[8];
    #pragma unroll
    for (int j = 0; j < 16; j++) { wl[j] = __ldg(&W2l[j]); wr[j] = __ldg(&W2r[j]); }
    #pragma unroll
    for (int j = 0; j < 4; j++) bb[j] = __ldg(&b2[j]);
    #pragma unroll
    for (int j = 0; j < 8; j++) w3[j] = __ldg(&W3l[j]);

    float2 p3loc[4];
    #pragma unroll
    for (int k = 0; k < 4; k++) {
        int i = 4 * t + k;
        float inv = ((const float*)&invv)[k];
        float4 s = g_sum2[i];
        float4 m = make_float4(s.x * inv, s.y * inv, s.z * inv, s.w * inv);
        float4 p = g_h1[i];
        float4 h;
        #pragma unroll
        for (int j = 0; j < 4; j++) {
            float v = bb[j];
            v += m.x * wl[0 * 4 + j] + m.y * wl[1 * 4 + j]
               + m.z * wl[2 * 4 + j] + m.w * wl[3 * 4 + j];
            v += p.x * wr[0 * 4 + j] + p.y * wr[1 * 4 + j]
               + p.z * wr[2 * 4 + j] + p.w * wr[3 * 4 + j];
            ((float*)&h)[j] = fmaxf(v, 0.f);
        }
        g_h2[i] = h;
        p3loc[k].x = h.x * w3[0] + h.y * w3[2] + h.z * w3[4] + h.w * w3[6];
        p3loc[k].y = h.x * w3[1] + h.y * w3[3] + h.z * w3[5] + h.w * w3[7];
    }
    ((float4*)g_p3)[2 * t]     = make_float4(p3loc[0].x, p3loc[0].y, p3loc[1].x, p3loc[1].y);
    ((float4*)g_p3)[2 * t + 1] = make_float4(p3loc[2].x, p3loc[2].y, p3loc[3].x, p3loc[3].y);
}

// -------- pass 3: sum3[dst] += p3[src] (dim 2), 4 edges/thread --------
__global__ void k_edge3(const int4* __restrict__ src4,
                        const int4* __restrict__ dst4) {
    int t = blockIdx.x * blockDim.x + threadIdx.x;
    if (t >= NE / 4) return;
    int4 s = src4[t];
    int4 d = dst4[t];
    float2 v0 = g_p3[s.x];
    float2 v1 = g_p3[s.y];
    float2 v2 = g_p3[s.z];
    float2 v3 = g_p3[s.w];
    red_add_v2(&g_sum3[d.x], v0.x, v0.y);
    red_add_v2(&g_sum3[d.y], v1.x, v1.y);
    red_add_v2(&g_sum3[d.z], v2.x, v2.y);
    red_add_v2(&g_sum3[d.w], v3.x, v3.y);
}

// -------- node 3: h3 = relu(mean3 terms); out = h3@Wc + bc; 4 nodes/thread --------
__global__ void k_node3(const float* __restrict__ b3,
                        const float* __restrict__ W3r,
                        const float* __restrict__ Wc, const float* __restrict__ bc,
                        float* __restrict__ out) {
    int t = blockIdx.x * blockDim.x + threadIdx.x;
    if (t >= NN / 4) return;
    float4 invv = ((const float4*)g_inv)[t];
    float4 s01 = ((const float4*)g_sum3)[2 * t];
    float4 s23 = ((const float4*)g_sum3)[2 * t + 1];

    float wr[8], b3l[2], wc[4], bcl[2];
    #pragma unroll
    for (int j = 0; j < 8; j++) wr[j] = __ldg(&W3r[j]);
    b3l[0] = __ldg(&b3[0]); b3l[1] = __ldg(&b3[1]);
    #pragma unroll
    for (int j = 0; j < 4; j++) wc[j] = __ldg(&Wc[j]);
    bcl[0] = __ldg(&bc[0]); bcl[1] = __ldg(&bc[1]);

    float2 sums[4] = { make_float2(s01.x, s01.y), make_float2(s01.z, s01.w),
                       make_float2(s23.x, s23.y), make_float2(s23.z, s23.w) };
    float2 oloc[4], hloc[4];
    #pragma unroll
    for (int k = 0; k < 4; k++) {
        int i = 4 * t + k;
        float inv = ((const float*)&invv)[k];
        float4 p = g_h2[i];
        float h0 = b3l[0] + sums[k].x * inv
                 + p.x * wr[0] + p.y * wr[2] + p.z * wr[4] + p.w * wr[6];
        float h1 = b3l[1] + sums[k].y * inv
                 + p.x * wr[1] + p.y * wr[3] + p.z * wr[5] + p.w * wr[7];
        h0 = fmaxf(h0, 0.f);
        h1 = fmaxf(h1, 0.f);
        hloc[k] = make_float2(h0, h1);
        oloc[k] = make_float2(h0 * wc[0] + h1 * wc[2] + bcl[0],
                              h0 * wc[1] + h1 * wc[3] + bcl[1]);
    }
    // output layout: (out [NN,2], h3 [NN,2]) flattened in order
    float4* out4 = (float4*)out;
    out4[2 * t]     = make_float4(oloc[0].x, oloc[0].y, oloc[1].x, oloc[1].y);
    out4[2 * t + 1] = make_float4(oloc[2].x, oloc[2].y, oloc[3].x, oloc[3].y);
    out4[NN / 2 + 2 * t]     = make_float4(hloc[0].x, hloc[0].y, hloc[1].x, hloc[1].y);
    out4[NN / 2 + 2 * t + 1] = make_float4(hloc[2].x, hloc[2].y, hloc[3].x, hloc[3].y);
}

extern "C" void kernel_launch(void* const* d_in, const int* in_sizes, int n_in,
                              void* d_out, int out_size) {
    const float* x   = (const float*)d_in[0];
    const int*   ei  = (const int*)d_in[1];   // int64 in reference -> delivered as int32 [2, E]
    const int4*  src4 = (const int4*)ei;
    const int4*  dst4 = (const int4*)(ei + NE);
    const float* W1l = (const float*)d_in[2];
    const float* b1  = (const float*)d_in[3];
    const float* W1r = (const float*)d_in[4];
    const float* W2l = (const float*)d_in[5];
    const float* b2  = (const float*)d_in[6];
    const float* W2r = (const float*)d_in[7];
    const float* W3l = (const float*)d_in[8];
    const float* b3  = (const float*)d_in[9];
    const float* W3r = (const float*)d_in[10];
    const float* Wc  = (const float*)d_in[11];
    const float* bc  = (const float*)d_in[12];
    float* out = (float*)d_out;

    const int BT = 256;
    const int gridN2 = (NN / 2 + BT - 1) / BT;
    const int gridN4 = (NN / 4 + BT - 1) / BT;
    const int gridE4 = (NE / 4 + BT - 1) / BT;

    k_zero<<<gridN2, BT>>>();
    k_edge1<<<gridE4, BT>>>(src4, dst4, x);
    k_node1<<<gridN4, BT>>>(x, W1l, b1, W1r);
    k_edge2<<<gridE4, BT>>>(src4, dst4);
    k_node2<<<gridN4, BT>>>(W2l, b2, W2r, W3l);
    k_edge3<<<gridE4, BT>>>(src4, dst4);
    k_node3<<<gridN4, BT>>>(b3, W3r, Wc, bc, out);
}

// round 8
// speedup vs baseline: 1.0578x; 1.0578x over previous
#include <cuda_runtime.h>
#include <cuda_bf16.h>

#define NN 1000000
#define NE 16000000

// -------- scratch (device globals; no allocation allowed) --------
__device__ float2 g_aggc[NN];    // {sum of x[src], count}
__device__ float4 g_h1[NN];
__device__ float4 g_sum2[NN];
__device__ float4 g_h2[NN];
__device__ float2 g_p3[NN];      // h2 @ W3l (projected to dim 2 before scatter)
__device__ float2 g_sum3[NN];    // accumulated projected values
__device__ float  g_inv[NN];     // 1 / max(count, 1)

__device__ __forceinline__ void red_add_v2(float2* addr, float a, float b) {
    asm volatile("red.global.add.v2.f32 [%0], {%1, %2};"
                 :: "l"(addr), "f"(a), "f"(b) : "memory");
}
__device__ __forceinline__ void red_add_v4(float4* addr, float4 v) {
    asm volatile("red.global.add.v4.f32 [%0], {%1, %2, %3, %4};"
                 :: "l"(addr), "f"(v.x), "f"(v.y), "f"(v.z), "f"(v.w) : "memory");
}

// -------- zero aggc only (immediately before edge1's scatter: warms L2) --------
__global__ void k_zero() {
    int i = blockIdx.x * blockDim.x + threadIdx.x;
    if (i < NN / 2) ((float4*)g_aggc)[i] = make_float4(0.f, 0.f, 0.f, 0.f);
}

// -------- pass 1: scatter {x[src], 1} to aggc[dst], 4 edges/thread --------
__global__ void k_edge1(const int4* __restrict__ src4,
                        const int4* __restrict__ dst4,
                        const float* __restrict__ x) {
    int t = blockIdx.x * blockDim.x + threadIdx.x;
    if (t >= NE / 4) return;
    int4 s = src4[t];
    int4 d = dst4[t];
    float x0 = __ldg(&x[s.x]);
    float x1 = __ldg(&x[s.y]);
    float x2 = __ldg(&x[s.z]);
    float x3 = __ldg(&x[s.w]);
    red_add_v2(&g_aggc[d.x], x0, 1.0f);
    red_add_v2(&g_aggc[d.y], x1, 1.0f);
    red_add_v2(&g_aggc[d.z], x2, 1.0f);
    red_add_v2(&g_aggc[d.w], x3, 1.0f);
}

// -------- node 1: h1 = relu(mean1*W1l + b1 + x*W1r); zero sum2 (warm for edge2) --------
__global__ void k_node1(const float* __restrict__ x,
                        const float* __restrict__ W1l, const float* __restrict__ b1,
                        const float* __restrict__ W1r) {
    int i = blockIdx.x * blockDim.x + threadIdx.x;
    if (i >= NN) return;
    float2 ac = g_aggc[i];
    float inv = 1.0f / fmaxf(ac.y, 1.0f);
    g_inv[i] = inv;
    float m = ac.x * inv;
    float xi = x[i];
    float4 h;
    h.x = fmaxf(m * W1l[0] + b1[0] + xi * W1r[0], 0.f);
    h.y = fmaxf(m * W1l[1] + b1[1] + xi * W1r[1], 0.f);
    h.z = fmaxf(m * W1l[2] + b1[2] + xi * W1r[2], 0.f);
    h.w = fmaxf(m * W1l[3] + b1[3] + xi * W1r[3], 0.f);
    g_h1[i] = h;
    g_sum2[i] = make_float4(0.f, 0.f, 0.f, 0.f);
}

// -------- pass 2: sum2[dst] += h1[src], 4 edges/thread --------
__global__ void k_edge2(const int4* __restrict__ src4,
                        const int4* __restrict__ dst4) {
    int t = blockIdx.x * blockDim.x + threadIdx.x;
    if (t >= NE / 4) return;
    int4 s = src4[t];
    int4 d = dst4[t];
    float4 v0 = g_h1[s.x];
    float4 v1 = g_h1[s.y];
    float4 v2 = g_h1[s.z];
    float4 v3 = g_h1[s.w];
    red_add_v4(&g_sum2[d.x], v0);
    red_add_v4(&g_sum2[d.y], v1);
    red_add_v4(&g_sum2[d.z], v2);
    red_add_v4(&g_sum2[d.w], v3);
}

// -------- node 2: h2 = relu(mean2@W2l + b2 + h1@W2r); p3 = h2@W3l; zero sum3 --------
__global__ void k_node2(const float* __restrict__ W2l, const float* __restrict__ b2,
                        const float* __restrict__ W2r, const float* __restrict__ W3l) {
    int i = blockIdx.x * blockDim.x + threadIdx.x;
    if (i >= NN) return;
    float inv = g_inv[i];
    float4 s = g_sum2[i];
    float4 m = make_float4(s.x * inv, s.y * inv, s.z * inv, s.w * inv);
    float4 p = g_h1[i];
    float4 h;
    #pragma unroll
    for (int j = 0; j < 4; j++) {
        float v = b2[j];
        v += m.x * W2l[0 * 4 + j] + m.y * W2l[1 * 4 + j]
           + m.z * W2l[2 * 4 + j] + m.w * W2l[3 * 4 + j];
        v += p.x * W2r[0 * 4 + j] + p.y * W2r[1 * 4 + j]
           + p.z * W2r[2 * 4 + j] + p.w * W2r[3 * 4 + j];
        v = fmaxf(v, 0.f);
        ((float*)&h)[j] = v;
    }
    g_h2[i] = h;
    // project to dim 2 now so the edge pass scatters 8B instead of 16B
    float2 q;
    q.x = h.x * W3l[0 * 2 + 0] + h.y * W3l[1 * 2 + 0]
        + h.z * W3l[2 * 2 + 0] + h.w * W3l[3 * 2 + 0];
    q.y = h.x * W3l[0 * 2 + 1] + h.y * W3l[1 * 2 + 1]
        + h.z * W3l[2 * 2 + 1] + h.w * W3l[3 * 2 + 1];
    g_p3[i] = q;
    g_sum3[i] = make_float2(0.f, 0.f);
}

// -------- pass 3: sum3[dst] += p3[src] (dim 2), 4 edges/thread --------
__global__ void k_edge3(const int4* __restrict__ src4,
                        const int4* __restrict__ dst4) {
    int t = blockIdx.x * blockDim.x + threadIdx.x;
    if (t >= NE / 4) return;
    int4 s = src4[t];
    int4 d = dst4[t];
    float2 v0 = g_p3[s.x];
    float2 v1 = g_p3[s.y];
    float2 v2 = g_p3[s.z];
    float2 v3 = g_p3[s.w];
    red_add_v2(&g_sum3[d.x], v0.x, v0.y);
    red_add_v2(&g_sum3[d.y], v1.x, v1.y);
    red_add_v2(&g_sum3[d.z], v2.x, v2.y);
    red_add_v2(&g_sum3[d.w], v3.x, v3.y);
}

// -------- node 3: h3 = relu(mean3@W3l + b3 + h2@W3r); out = h3@Wc + bc --------
__global__ void k_node3(const float* __restrict__ b3,
                        const float* __restrict__ W3r,
                        const float* __restrict__ Wc, const float* __restrict__ bc,
                        float* __restrict__ out) {
    int i = blockIdx.x * blockDim.x + threadIdx.x;
    if (i >= NN) return;
    float inv = g_inv[i];
    float2 s = g_sum3[i];        // already projected through W3l
    float4 p = g_h2[i];
    float h3[2];
    #pragma unroll
    for (int j = 0; j < 2; j++) {
        float v = b3[j] + ((j == 0) ? s.x : s.y) * inv;
        v += p.x * W3r[0 * 2 + j] + p.y * W3r[1 * 2 + j]
           + p.z * W3r[2 * 2 + j] + p.w * W3r[3 * 2 + j];
        h3[j] = fmaxf(v, 0.f);
    }
    float2 o;
    o.x = h3[0] * Wc[0] + h3[1] * Wc[2] + bc[0];
    o.y = h3[0] * Wc[1] + h3[1] * Wc[3] + bc[1];
    // output layout: (out [NN,2], h3 [NN,2]) flattened in order
    ((float2*)out)[i] = o;
    ((float2*)out)[NN + i] = make_float2(h3[0], h3[1]);
}

extern "C" void kernel_launch(void* const* d_in, const int* in_sizes, int n_in,
                              void* d_out, int out_size) {
    const float* x   = (const float*)d_in[0];
    const int*   ei  = (const int*)d_in[1];   // int64 in reference -> delivered as int32 [2, E]
    const int4*  src4 = (const int4*)ei;
    const int4*  dst4 = (const int4*)(ei + NE);
    const float* W1l = (const float*)d_in[2];
    const float* b1  = (const float*)d_in[3];
    const float* W1r = (const float*)d_in[4];
    const float* W2l = (const float*)d_in[5];
    const float* b2  = (const float*)d_in[6];
    const float* W2r = (const float*)d_in[7];
    const float* W3l = (const float*)d_in[8];
    const float* b3  = (const float*)d_in[9];
    const float* W3r = (const float*)d_in[10];
    const float* Wc  = (const float*)d_in[11];
    const float* bc  = (const float*)d_in[12];
    float* out = (float*)d_out;

    const int BT = 256;
    const int gridN  = (NN + BT - 1) / BT;
    const int gridN2 = (NN / 2 + BT - 1) / BT;
    const int gridE4 = (NE / 4 + BT - 1) / BT;

    k_zero<<<gridN2, BT>>>();
    k_edge1<<<gridE4, BT>>>(src4, dst4, x);
    k_node1<<<gridN, BT>>>(x, W1l, b1, W1r);
    k_edge2<<<gridE4, BT>>>(src4, dst4);
    k_node2<<<gridN, BT>>>(W2l, b2, W2r, W3l);
    k_edge3<<<gridE4, BT>>>(src4, dst4);
    k_node3<<<gridN, BT>>>(b3, W3r, Wc, bc, out);
}

// round 10
// speedup vs baseline: 1.0640x; 1.0058x over previous
#include <cuda_runtime.h>
#include <cuda_bf16.h>

#define NN 1000000
#define NE 16000000

// -------- scratch (device globals; no allocation allowed) --------
__device__ float2 g_aggc[NN];    // {sum of x[src], count}
__device__ float4 g_h1[NN];
__device__ float4 g_sum2[NN];
__device__ float4 g_h2[NN];
__device__ float2 g_p3[NN];      // h2 @ W3l (projected to dim 2 before scatter)
__device__ float2 g_sum3[NN];    // accumulated projected values
__device__ float  g_inv[NN];     // 1 / max(count, 1)

__device__ __forceinline__ void red_add_v2(float2* addr, float a, float b) {
    asm volatile("red.global.add.v2.f32 [%0], {%1, %2};"
                 :: "l"(addr), "f"(a), "f"(b) : "memory");
}
__device__ __forceinline__ void red_add_v4(float4* addr, float4 v) {
    asm volatile("red.global.add.v4.f32 [%0], {%1, %2, %3, %4};"
                 :: "l"(addr), "f"(v.x), "f"(v.y), "f"(v.z), "f"(v.w) : "memory");
}
// streaming (evict-first) load for the one-shot edge index stream
__device__ __forceinline__ int4 ldcs_int4(const int4* p) {
    int4 v;
    asm volatile("ld.global.cs.v4.s32 {%0,%1,%2,%3}, [%4];"
                 : "=r"(v.x), "=r"(v.y), "=r"(v.z), "=r"(v.w) : "l"(p));
    return v;
}
// L2 evict-last cache policy (valid for any width via cache_hint form)
__device__ __forceinline__ unsigned long long mk_evict_last_policy() {
    unsigned long long pol;
    asm("createpolicy.fractional.L2::evict_last.b64 %0, 1.0;" : "=l"(pol));
    return pol;
}
__device__ __forceinline__ float ldel_f(const float* p, unsigned long long pol) {
    float v;
    asm volatile("ld.global.L2::cache_hint.f32 %0, [%1], %2;"
                 : "=f"(v) : "l"(p), "l"(pol));
    return v;
}
__device__ __forceinline__ float2 ldel_f2(const float2* p, unsigned long long pol) {
    float2 v;
    asm volatile("ld.global.L2::cache_hint.v2.f32 {%0,%1}, [%2], %3;"
                 : "=f"(v.x), "=f"(v.y) : "l"(p), "l"(pol));
    return v;
}
__device__ __forceinline__ float4 ldel_f4(const float4* p, unsigned long long pol) {
    float4 v;
    asm volatile("ld.global.L2::cache_hint.v4.f32 {%0,%1,%2,%3}, [%4], %5;"
                 : "=f"(v.x), "=f"(v.y), "=f"(v.z), "=f"(v.w) : "l"(p), "l"(pol));
    return v;
}

// -------- zero aggc only (immediately before edge1's scatter: warms L2) --------
__global__ void k_zero() {
    int i = blockIdx.x * blockDim.x + threadIdx.x;
    if (i < NN / 2) ((float4*)g_aggc)[i] = make_float4(0.f, 0.f, 0.f, 0.f);
}

// -------- pass 1: scatter {x[src], 1} to aggc[dst], 4 edges/thread --------
__global__ void k_edge1(const int4* __restrict__ src4,
                        const int4* __restrict__ dst4,
                        const float* __restrict__ x) {
    int t = blockIdx.x * blockDim.x + threadIdx.x;
    if (t >= NE / 4) return;
    unsigned long long pol = mk_evict_last_policy();
    int4 s = ldcs_int4(&src4[t]);
    int4 d = ldcs_int4(&dst4[t]);
    float x0 = ldel_f(&x[s.x], pol);
    float x1 = ldel_f(&x[s.y], pol);
    float x2 = ldel_f(&x[s.z], pol);
    float x3 = ldel_f(&x[s.w], pol);
    red_add_v2(&g_aggc[d.x], x0, 1.0f);
    red_add_v2(&g_aggc[d.y], x1, 1.0f);
    red_add_v2(&g_aggc[d.z], x2, 1.0f);
    red_add_v2(&g_aggc[d.w], x3, 1.0f);
}

// -------- node 1: h1 = relu(mean1*W1l + b1 + x*W1r); zero sum2 (warm for edge2) --------
__global__ void k_node1(const float* __restrict__ x,
                        const float* __restrict__ W1l, const float* __restrict__ b1,
                        const float* __restrict__ W1r) {
    int i = blockIdx.x * blockDim.x + threadIdx.x;
    if (i >= NN) return;
    float2 ac = g_aggc[i];
    float inv = 1.0f / fmaxf(ac.y, 1.0f);
    g_inv[i] = inv;
    float m = ac.x * inv;
    float xi = x[i];
    float4 h;
    h.x = fmaxf(m * W1l[0] + b1[0] + xi * W1r[0], 0.f);
    h.y = fmaxf(m * W1l[1] + b1[1] + xi * W1r[1], 0.f);
    h.z = fmaxf(m * W1l[2] + b1[2] + xi * W1r[2], 0.f);
    h.w = fmaxf(m * W1l[3] + b1[3] + xi * W1r[3], 0.f);
    g_h1[i] = h;
    g_sum2[i] = make_float4(0.f, 0.f, 0.f, 0.f);
}

// -------- pass 2: sum2[dst] += h1[src], 4 edges/thread --------
__global__ void k_edge2(const int4* __restrict__ src4,
                        const int4* __restrict__ dst4) {
    int t = blockIdx.x * blockDim.x + threadIdx.x;
    if (t >= NE / 4) return;
    unsigned long long pol = mk_evict_last_policy();
    int4 s = ldcs_int4(&src4[t]);
    int4 d = ldcs_int4(&dst4[t]);
    float4 v0 = ldel_f4(&g_h1[s.x], pol);
    float4 v1 = ldel_f4(&g_h1[s.y], pol);
    float4 v2 = ldel_f4(&g_h1[s.z], pol);
    float4 v3 = ldel_f4(&g_h1[s.w], pol);
    red_add_v4(&g_sum2[d.x], v0);
    red_add_v4(&g_sum2[d.y], v1);
    red_add_v4(&g_sum2[d.z], v2);
    red_add_v4(&g_sum2[d.w], v3);
}

// -------- node 2: h2 = relu(mean2@W2l + b2 + h1@W2r); p3 = h2@W3l; zero sum3 --------
__global__ void k_node2(const float* __restrict__ W2l, const float* __restrict__ b2,
                        const float* __restrict__ W2r, const float* __restrict__ W3l) {
    int i = blockIdx.x * blockDim.x + threadIdx.x;
    if (i >= NN) return;
    float inv = g_inv[i];
    float4 s = g_sum2[i];
    float4 m = make_float4(s.x * inv, s.y * inv, s.z * inv, s.w * inv);
    float4 p = g_h1[i];
    float4 h;
    #pragma unroll
    for (int j = 0; j < 4; j++) {
        float v = b2[j];
        v += m.x * W2l[0 * 4 + j] + m.y * W2l[1 * 4 + j]
           + m.z * W2l[2 * 4 + j] + m.w * W2l[3 * 4 + j];
        v += p.x * W2r[0 * 4 + j] + p.y * W2r[1 * 4 + j]
           + p.z * W2r[2 * 4 + j] + p.w * W2r[3 * 4 + j];
        v = fmaxf(v, 0.f);
        ((float*)&h)[j] = v;
    }
    g_h2[i] = h;
    // project to dim 2 now so the edge pass scatters 8B instead of 16B
    float2 q;
    q.x = h.x * W3l[0 * 2 + 0] + h.y * W3l[1 * 2 + 0]
        + h.z * W3l[2 * 2 + 0] + h.w * W3l[3 * 2 + 0];
    q.y = h.x * W3l[0 * 2 + 1] + h.y * W3l[1 * 2 + 1]
        + h.z * W3l[2 * 2 + 1] + h.w * W3l[3 * 2 + 1];
    g_p3[i] = q;
    g_sum3[i] = make_float2(0.f, 0.f);
}

// -------- pass 3: sum3[dst] += p3[src] (dim 2), 4 edges/thread --------
__global__ void k_edge3(const int4* __restrict__ src4,
                        const int4* __restrict__ dst4) {
    int t = blockIdx.x * blockDim.x + threadIdx.x;
    if (t >= NE / 4) return;
    unsigned long long pol = mk_evict_last_policy();
    int4 s = ldcs_int4(&src4[t]);
    int4 d = ldcs_int4(&dst4[t]);
    float2 v0 = ldel_f2(&g_p3[s.x], pol);
    float2 v1 = ldel_f2(&g_p3[s.y], pol);
    float2 v2 = ldel_f2(&g_p3[s.z], pol);
    float2 v3 = ldel_f2(&g_p3[s.w], pol);
    red_add_v2(&g_sum3[d.x], v0.x, v0.y);
    red_add_v2(&g_sum3[d.y], v1.x, v1.y);
    red_add_v2(&g_sum3[d.z], v2.x, v2.y);
    red_add_v2(&g_sum3[d.w], v3.x, v3.y);
}

// -------- node 3: h3 = relu(mean3@W3l + b3 + h2@W3r); out = h3@Wc + bc --------
__global__ void k_node3(const float* __restrict__ b3,
                        const float* __restrict__ W3r,
                        const float* __restrict__ Wc, const float* __restrict__ bc,
                        float* __restrict__ out) {
    int i = blockIdx.x * blockDim.x + threadIdx.x;
    if (i >= NN) return;
    float inv = g_inv[i];
    float2 s = g_sum3[i];        // already projected through W3l
    float4 p = g_h2[i];
    float h3[2];
    #pragma unroll
    for (int j = 0; j < 2; j++) {
        float v = b3[j] + ((j == 0) ? s.x : s.y) * inv;
        v += p.x * W3r[0 * 2 + j] + p.y * W3r[1 * 2 + j]
           + p.z * W3r[2 * 2 + j] + p.w * W3r[3 * 2 + j];
        h3[j] = fmaxf(v, 0.f);
    }
    float2 o;
    o.x = h3[0] * Wc[0] + h3[1] * Wc[2] + bc[0];
    o.y = h3[0] * Wc[1] + h3[1] * Wc[3] + bc[1];
    // output layout: (out [NN,2], h3 [NN,2]) flattened in order
    ((float2*)out)[i] = o;
    ((float2*)out)[NN + i] = make_float2(h3[0], h3[1]);
}

extern "C" void kernel_launch(void* const* d_in, const int* in_sizes, int n_in,
                              void* d_out, int out_size) {
    const float* x   = (const float*)d_in[0];
    const int*   ei  = (const int*)d_in[1];   // int64 in reference -> delivered as int32 [2, E]
    const int4*  src4 = (const int4*)ei;
    const int4*  dst4 = (const int4*)(ei + NE);
    const float* W1l = (const float*)d_in[2];
    const float* b1  = (const float*)d_in[3];
    const float* W1r = (const float*)d_in[4];
    const float* W2l = (const float*)d_in[5];
    const float* b2  = (const float*)d_in[6];
    const float* W2r = (const float*)d_in[7];
    const float* W3l = (const float*)d_in[8];
    const float* b3  = (const float*)d_in[9];
    const float* W3r = (const float*)d_in[10];
    const float* Wc  = (const float*)d_in[11];
    const float* bc  = (const float*)d_in[12];
    float* out = (float*)d_out;

    const int BT = 256;
    const int gridN  = (NN + BT - 1) / BT;
    const int gridN2 = (NN / 2 + BT - 1) / BT;
    const int gridE4 = (NE / 4 + BT - 1) / BT;

    k_zero<<<gridN2, BT>>>();
    k_edge1<<<gridE4, BT>>>(src4, dst4, x);
    k_node1<<<gridN, BT>>>(x, W1l, b1, W1r);
    k_edge2<<<gridE4, BT>>>(src4, dst4);
    k_node2<<<gridN, BT>>>(W2l, b2, W2r, W3l);
    k_edge3<<<gridE4, BT>>>(src4, dst4);
    k_node3<<<gridN, BT>>>(b3, W3r, Wc, bc, out);
}